// round 13
// baseline (speedup 1.0000x reference)
#include <cuda_runtime.h>
#include <cuda_bf16.h>

#define N_NODES 100000
#define N_EDGES 1600000
#define IN_DIM  128
#define HID_DIM 64
#define OUT_DIM 40
#define SCAN_T  1024

// ---------------- scratch (static device globals; no runtime alloc) --------
__device__              int    g_is64;
__device__              int    g_cd  [N_NODES];      // dst histogram (degree); zero-init, reset each call
__device__              int    g_cs  [N_NODES];      // src histogram; zero-init, reset each call
__device__              int    g_cur [N_NODES];      // fill cursor (rebuilt each call)
__device__ __align__(16) float g_dinv[N_NODES];
__device__              int    g_src [N_EDGES];
__device__              int    g_dst [N_EDGES];
__device__ __align__(16) int4  g_ems [N_EDGES];      // {src, dst, bits(norm), 0} sorted by src
__device__ __align__(16) float g_h1  [(size_t)N_NODES * HID_DIM];   // x@W1
__device__ __align__(16) float g_agg1[(size_t)N_NODES * HID_DIM];   // layer1 agg
__device__ __align__(16) float g_h2  [(size_t)N_NODES * OUT_DIM];   // relu(agg1+b1)@W2

__device__ __forceinline__ void redg_v4(float* p, float a, float b, float c, float d) {
    asm volatile("red.global.add.v4.f32 [%0], {%1, %2, %3, %4};"
                 :: "l"(p), "f"(a), "f"(b), "f"(c), "f"(d) : "memory");
}

// ---------------- dtype detection: int32 vs int64 edge_index ---------------
__global__ void k_detect(const unsigned* __restrict__ w) {
    if (threadIdx.x == 0 && blockIdx.x == 0) {
        int all0 = 1;
        for (int i = 0; i < 64; i++)
            if (w[2 * i + 1] != 0u) { all0 = 0; break; }
        g_is64 = all0;
    }
}

// extract src/dst as int32 (either stored width) + both histograms
__global__ void k_extract(const unsigned* __restrict__ w) {
    int e = blockIdx.x * blockDim.x + threadIdx.x;
    if (e >= N_EDGES) return;
    int s, d;
    if (g_is64) {
        s = (int)w[2 * e];                           // low word of int64
        d = (int)w[2 * (N_EDGES + e)];
    } else {
        s = (int)w[e];
        d = (int)w[N_EDGES + e];
    }
    g_src[e] = s;
    g_dst[e] = d;
    atomicAdd(&g_cd[d], 1);
    atomicAdd(&g_cs[s], 1);
}

// dinv from in-degree; resets g_cd so next call starts from zero
__global__ void k_rsqrt() {
    int i = blockIdx.x * blockDim.x + threadIdx.x;
    if (i < N_NODES) {
        g_dinv[i] = rsqrtf((float)g_cd[i] + 1.0f);   // + self loop
        g_cd[i] = 0;
    }
}

// single-block exclusive scan of g_cs -> g_cur; resets g_cs
__global__ __launch_bounds__(SCAN_T) void k_scan() {
    __shared__ int part[SCAN_T];
    int t = threadIdx.x;
    const int chunk = (N_NODES + SCAN_T - 1) / SCAN_T;   // 98
    int lo = t * chunk;
    int hi = min(lo + chunk, N_NODES);
    int sum = 0;
    for (int i = lo; i < hi; i++) sum += g_cs[i];
    part[t] = sum;
    __syncthreads();
    for (int off = 1; off < SCAN_T; off <<= 1) {
        int other = (t >= off) ? part[t - off] : 0;
        __syncthreads();
        part[t] += other;
        __syncthreads();
    }
    int run = part[t] - sum;                             // exclusive offset
    for (int i = lo; i < hi; i++) {
        g_cur[i] = run;
        run += g_cs[i];
        g_cs[i] = 0;                                     // reset for next call
    }
}

// scatter edges into src-sorted slots with precomputed norm
__global__ void k_fill() {
    int e = blockIdx.x * blockDim.x + threadIdx.x;
    if (e >= N_EDGES) return;
    int s = g_src[e];
    int d = g_dst[e];
    int slot = atomicAdd(&g_cur[s], 1);
    float nrm = g_dinv[s] * g_dinv[d];
    g_ems[slot] = make_int4(s, d, __float_as_int(nrm), 0);
}

// ---------------- layer 1 GEMM: h1 = x @ W1; agg1 init with self loop ------
__global__ __launch_bounds__(256) void k_gemm1(const float* __restrict__ x,
                                               const float* __restrict__ W1) {
    __shared__ float Ws[IN_DIM * HID_DIM];          // 32 KB
    {
        float4* dsh = (float4*)Ws;
        const float4* ssh = (const float4*)W1;
        for (int i = threadIdx.x; i < IN_DIM * HID_DIM / 4; i += blockDim.x)
            dsh[i] = ssh[i];
    }
    __syncthreads();

    int node = blockIdx.x * blockDim.x + threadIdx.x;
    if (node >= N_NODES) return;

    float acc[HID_DIM];
#pragma unroll
    for (int j = 0; j < HID_DIM; j++) acc[j] = 0.0f;

    const float4* xr = (const float4*)(x + (size_t)node * IN_DIM);
#pragma unroll 2
    for (int kk = 0; kk < IN_DIM / 4; ++kk) {
        float4 xv = xr[kk];
        float xs[4] = {xv.x, xv.y, xv.z, xv.w};
#pragma unroll
        for (int q = 0; q < 4; ++q) {
            const float4* wr = (const float4*)&Ws[(kk * 4 + q) * HID_DIM];
#pragma unroll
            for (int j4 = 0; j4 < HID_DIM / 4; ++j4) {
                float4 w = wr[j4];                  // warp-broadcast LDS
                acc[4 * j4 + 0] += xs[q] * w.x;
                acc[4 * j4 + 1] += xs[q] * w.y;
                acc[4 * j4 + 2] += xs[q] * w.z;
                acc[4 * j4 + 3] += xs[q] * w.w;
            }
        }
    }

    float di = g_dinv[node];
    float sl = di * di;                             // self-loop coefficient
    size_t base = (size_t)node * HID_DIM;
#pragma unroll
    for (int j4 = 0; j4 < HID_DIM / 4; ++j4) {
        float4 h;
        h.x = acc[4 * j4 + 0]; h.y = acc[4 * j4 + 1];
        h.z = acc[4 * j4 + 2]; h.w = acc[4 * j4 + 3];
        *(float4*)&g_h1[base + 4 * j4] = h;
        float4 a;
        a.x = h.x * sl; a.y = h.y * sl; a.z = h.z * sl; a.w = h.w * sl;
        *(float4*)&g_agg1[base + 4 * j4] = a;
    }
}

// ---- layer 1 edge aggregation: 16 threads/edge, src-sorted (hot gathers) --
__global__ __launch_bounds__(256) void k_agg1() {
    int idx = blockIdx.x * blockDim.x + threadIdx.x;    // E * 16 items
    if (idx >= N_EDGES * 16) return;
    int e = idx >> 4;
    int c = (idx & 15) << 2;                            // float offset, 16B aligned
    int4 em = g_ems[e];                                 // one broadcast LDG.128
    float nrm = __int_as_float(em.z);
    float4 v = *(const float4*)&g_h1[(size_t)em.x * HID_DIM + c];  // L1/L2 hot
    float* p = &g_agg1[(size_t)em.y * HID_DIM + c];
    redg_v4(p, v.x * nrm, v.y * nrm, v.z * nrm, v.w * nrm);
}

// ------- layer 2 GEMM: h2 = relu(agg1 + b1) @ W2; out init = h2*d^2 + b2 ---
__global__ __launch_bounds__(256) void k_gemm2(const float* __restrict__ W2,
                                               const float* __restrict__ b1,
                                               const float* __restrict__ b2,
                                               float* __restrict__ out) {
    __shared__ float Ws[HID_DIM * OUT_DIM];         // 10 KB
    __shared__ float b1s[HID_DIM];
    __shared__ float b2s[OUT_DIM];
    for (int i = threadIdx.x; i < HID_DIM * OUT_DIM; i += blockDim.x) Ws[i] = W2[i];
    for (int i = threadIdx.x; i < HID_DIM; i += blockDim.x) b1s[i] = b1[i];
    for (int i = threadIdx.x; i < OUT_DIM; i += blockDim.x) b2s[i] = b2[i];
    __syncthreads();

    int node = blockIdx.x * blockDim.x + threadIdx.x;
    if (node >= N_NODES) return;

    float acc[OUT_DIM];
#pragma unroll
    for (int j = 0; j < OUT_DIM; j++) acc[j] = 0.0f;

    size_t ibase = (size_t)node * HID_DIM;
#pragma unroll 2
    for (int k4 = 0; k4 < HID_DIM / 4; ++k4) {
        float4 a = *(const float4*)&g_agg1[ibase + 4 * k4];
        float vin[4];
        vin[0] = fmaxf(a.x + b1s[4 * k4 + 0], 0.0f);
        vin[1] = fmaxf(a.y + b1s[4 * k4 + 1], 0.0f);
        vin[2] = fmaxf(a.z + b1s[4 * k4 + 2], 0.0f);
        vin[3] = fmaxf(a.w + b1s[4 * k4 + 3], 0.0f);
#pragma unroll
        for (int q = 0; q < 4; ++q) {
            const float4* wr = (const float4*)&Ws[(4 * k4 + q) * OUT_DIM];
#pragma unroll
            for (int j4 = 0; j4 < OUT_DIM / 4; ++j4) {
                float4 w = wr[j4];
                acc[4 * j4 + 0] += vin[q] * w.x;
                acc[4 * j4 + 1] += vin[q] * w.y;
                acc[4 * j4 + 2] += vin[q] * w.z;
                acc[4 * j4 + 3] += vin[q] * w.w;
            }
        }
    }

    float di = g_dinv[node];
    float sl = di * di;
    size_t ob = (size_t)node * OUT_DIM;
#pragma unroll
    for (int j4 = 0; j4 < OUT_DIM / 4; ++j4) {
        float4 h;
        h.x = acc[4 * j4 + 0]; h.y = acc[4 * j4 + 1];
        h.z = acc[4 * j4 + 2]; h.w = acc[4 * j4 + 3];
        *(float4*)&g_h2[ob + 4 * j4] = h;
        float4 o;
        o.x = h.x * sl + b2s[4 * j4 + 0];
        o.y = h.y * sl + b2s[4 * j4 + 1];
        o.z = h.z * sl + b2s[4 * j4 + 2];
        o.w = h.w * sl + b2s[4 * j4 + 3];
        *(float4*)&out[ob + 4 * j4] = o;
    }
}

// ---- layer 2 edge aggregation: 10 threads/edge, src-sorted ----------------
__global__ __launch_bounds__(320) void k_agg2(float* __restrict__ out) {
    int idx = blockIdx.x * blockDim.x + threadIdx.x;    // E * 10 items
    int e = idx / 10;
    if (e >= N_EDGES) return;
    int c = (idx - e * 10) * 4;                         // float offset, 16B aligned
    int4 em = g_ems[e];                                 // one broadcast LDG.128
    float nrm = __int_as_float(em.z);
    float4 v = *(const float4*)&g_h2[(size_t)em.x * OUT_DIM + c];  // L1/L2 hot
    float* p = &out[(size_t)em.y * OUT_DIM + c];
    redg_v4(p, v.x * nrm, v.y * nrm, v.z * nrm, v.w * nrm);
}

// ---------------- launcher -------------------------------------------------
extern "C" void kernel_launch(void* const* d_in, const int* in_sizes, int n_in,
                              void* d_out, int out_size) {
    const float*    x  = (const float*)d_in[0];
    const unsigned* ei = (const unsigned*)d_in[1];   // int32 OR int64 words
    const float*    W1 = (const float*)d_in[2];
    const float*    b1 = (const float*)d_in[3];
    const float*    W2 = (const float*)d_in[4];
    const float*    b2 = (const float*)d_in[5];
    float* out = (float*)d_out;

    const int T = 256;
    k_detect <<<1, 32>>>(ei);
    k_extract<<<(N_EDGES + T - 1) / T, T>>>(ei);
    k_rsqrt  <<<(N_NODES + T - 1) / T, T>>>();
    k_scan   <<<1, SCAN_T>>>();
    k_fill   <<<(N_EDGES + T - 1) / T, T>>>();
    k_gemm1  <<<(N_NODES + T - 1) / T, T>>>(x, W1);
    k_agg1   <<<(N_EDGES * 16 + T - 1) / T, T>>>();
    k_gemm2  <<<(N_NODES + T - 1) / T, T>>>(W2, b1, b2, out);
    k_agg2   <<<(N_EDGES * 10 + 319) / 320, 320>>>(out);
}

// round 14
// speedup vs baseline: 1.5827x; 1.5827x over previous
#include <cuda_runtime.h>
#include <cuda_bf16.h>

#define N_NODES 100000
#define N_EDGES 1600000
#define IN_DIM  128
#define HID_DIM 64
#define OUT_DIM 40

// ---------------- scratch (static device globals; no runtime alloc) --------
__device__              int    g_is64;
__device__              int    g_cd  [N_NODES];      // dst histogram; zero-init, reset each call
__device__ __align__(16) float g_dinv[N_NODES];
__device__ __align__(8)  int2  g_em  [N_EDGES];      // {src, dst}
__device__ __align__(16) float g_h1  [(size_t)N_NODES * HID_DIM];   // x@W1
__device__ __align__(16) float g_agg1[(size_t)N_NODES * HID_DIM];   // layer1 agg
__device__ __align__(16) float g_h2  [(size_t)N_NODES * OUT_DIM];   // relu(agg1+b1)@W2

__device__ __forceinline__ void redg_v4(float* p, float a, float b, float c, float d) {
    asm volatile("red.global.add.v4.f32 [%0], {%1, %2, %3, %4};"
                 :: "l"(p), "f"(a), "f"(b), "f"(c), "f"(d) : "memory");
}

// ---------------- dtype detection: int32 vs int64 edge_index ---------------
__global__ void k_detect(const unsigned* __restrict__ w) {
    if (threadIdx.x == 0 && blockIdx.x == 0) {
        int all0 = 1;
        for (int i = 0; i < 64; i++)
            if (w[2 * i + 1] != 0u) { all0 = 0; break; }
        g_is64 = all0;
    }
}

// extract {src,dst} as int2 (either stored width) + dst histogram
__global__ void k_extract(const unsigned* __restrict__ w) {
    int e = blockIdx.x * blockDim.x + threadIdx.x;
    if (e >= N_EDGES) return;
    int s, d;
    if (g_is64) {
        s = (int)w[2 * e];                           // low word of int64
        d = (int)w[2 * (N_EDGES + e)];
    } else {
        s = (int)w[e];
        d = (int)w[N_EDGES + e];
    }
    g_em[e] = make_int2(s, d);
    atomicAdd(&g_cd[d], 1);                          // int REDG
}

// dinv from in-degree; resets g_cd so the next (graph-replayed) call is clean
__global__ void k_rsqrt() {
    int i = blockIdx.x * blockDim.x + threadIdx.x;
    if (i < N_NODES) {
        g_dinv[i] = rsqrtf((float)g_cd[i] + 1.0f);   // + self loop
        g_cd[i] = 0;
    }
}

// ---------------- layer 1 GEMM: h1 = x @ W1; agg1 init with self loop ------
__global__ __launch_bounds__(256) void k_gemm1(const float* __restrict__ x,
                                               const float* __restrict__ W1) {
    __shared__ float Ws[IN_DIM * HID_DIM];          // 32 KB
    {
        float4* dsh = (float4*)Ws;
        const float4* ssh = (const float4*)W1;
        for (int i = threadIdx.x; i < IN_DIM * HID_DIM / 4; i += blockDim.x)
            dsh[i] = ssh[i];
    }
    __syncthreads();

    int node = blockIdx.x * blockDim.x + threadIdx.x;
    if (node >= N_NODES) return;

    float acc[HID_DIM];
#pragma unroll
    for (int j = 0; j < HID_DIM; j++) acc[j] = 0.0f;

    const float4* xr = (const float4*)(x + (size_t)node * IN_DIM);
#pragma unroll 2
    for (int kk = 0; kk < IN_DIM / 4; ++kk) {
        float4 xv = xr[kk];
        float xs[4] = {xv.x, xv.y, xv.z, xv.w};
#pragma unroll
        for (int q = 0; q < 4; ++q) {
            const float4* wr = (const float4*)&Ws[(kk * 4 + q) * HID_DIM];
#pragma unroll
            for (int j4 = 0; j4 < HID_DIM / 4; ++j4) {
                float4 w = wr[j4];                  // warp-broadcast LDS
                acc[4 * j4 + 0] += xs[q] * w.x;
                acc[4 * j4 + 1] += xs[q] * w.y;
                acc[4 * j4 + 2] += xs[q] * w.z;
                acc[4 * j4 + 3] += xs[q] * w.w;
            }
        }
    }

    float di = g_dinv[node];
    float sl = di * di;                             // self-loop coefficient
    size_t base = (size_t)node * HID_DIM;
#pragma unroll
    for (int j4 = 0; j4 < HID_DIM / 4; ++j4) {
        float4 h;
        h.x = acc[4 * j4 + 0]; h.y = acc[4 * j4 + 1];
        h.z = acc[4 * j4 + 2]; h.w = acc[4 * j4 + 3];
        *(float4*)&g_h1[base + 4 * j4] = h;
        float4 a;
        a.x = h.x * sl; a.y = h.y * sl; a.z = h.z * sl; a.w = h.w * sl;
        *(float4*)&g_agg1[base + 4 * j4] = a;
    }
}

// ------- layer 1 edge aggregation: 16 threads/edge, vector REDG.128 --------
__global__ __launch_bounds__(256) void k_agg1() {
    int idx = blockIdx.x * blockDim.x + threadIdx.x;    // E * 16 items
    if (idx >= N_EDGES * 16) return;
    int e = idx >> 4;
    int c = (idx & 15) << 2;                            // float offset, 16B aligned
    int2 em = g_em[e];                                  // one broadcast LDG.64
    float nrm = g_dinv[em.x] * g_dinv[em.y];            // L2-hot broadcast loads
    float4 v = *(const float4*)&g_h1[(size_t)em.x * HID_DIM + c];
    float* p = &g_agg1[(size_t)em.y * HID_DIM + c];
    redg_v4(p, v.x * nrm, v.y * nrm, v.z * nrm, v.w * nrm);
}

// ------- layer 2 GEMM: h2 = relu(agg1 + b1) @ W2; out init = h2*d^2 + b2 ---
__global__ __launch_bounds__(256) void k_gemm2(const float* __restrict__ W2,
                                               const float* __restrict__ b1,
                                               const float* __restrict__ b2,
                                               float* __restrict__ out) {
    __shared__ float Ws[HID_DIM * OUT_DIM];         // 10 KB
    __shared__ float b1s[HID_DIM];
    __shared__ float b2s[OUT_DIM];
    for (int i = threadIdx.x; i < HID_DIM * OUT_DIM; i += blockDim.x) Ws[i] = W2[i];
    for (int i = threadIdx.x; i < HID_DIM; i += blockDim.x) b1s[i] = b1[i];
    for (int i = threadIdx.x; i < OUT_DIM; i += blockDim.x) b2s[i] = b2[i];
    __syncthreads();

    int node = blockIdx.x * blockDim.x + threadIdx.x;
    if (node >= N_NODES) return;

    float acc[OUT_DIM];
#pragma unroll
    for (int j = 0; j < OUT_DIM; j++) acc[j] = 0.0f;

    size_t ibase = (size_t)node * HID_DIM;
#pragma unroll 2
    for (int k4 = 0; k4 < HID_DIM / 4; ++k4) {
        float4 a = *(const float4*)&g_agg1[ibase + 4 * k4];
        float vin[4];
        vin[0] = fmaxf(a.x + b1s[4 * k4 + 0], 0.0f);
        vin[1] = fmaxf(a.y + b1s[4 * k4 + 1], 0.0f);
        vin[2] = fmaxf(a.z + b1s[4 * k4 + 2], 0.0f);
        vin[3] = fmaxf(a.w + b1s[4 * k4 + 3], 0.0f);
#pragma unroll
        for (int q = 0; q < 4; ++q) {
            const float4* wr = (const float4*)&Ws[(4 * k4 + q) * OUT_DIM];
#pragma unroll
            for (int j4 = 0; j4 < OUT_DIM / 4; ++j4) {
                float4 w = wr[j4];
                acc[4 * j4 + 0] += vin[q] * w.x;
                acc[4 * j4 + 1] += vin[q] * w.y;
                acc[4 * j4 + 2] += vin[q] * w.z;
                acc[4 * j4 + 3] += vin[q] * w.w;
            }
        }
    }

    float di = g_dinv[node];
    float sl = di * di;
    size_t ob = (size_t)node * OUT_DIM;
#pragma unroll
    for (int j4 = 0; j4 < OUT_DIM / 4; ++j4) {
        float4 h;
        h.x = acc[4 * j4 + 0]; h.y = acc[4 * j4 + 1];
        h.z = acc[4 * j4 + 2]; h.w = acc[4 * j4 + 3];
        *(float4*)&g_h2[ob + 4 * j4] = h;
        float4 o;
        o.x = h.x * sl + b2s[4 * j4 + 0];
        o.y = h.y * sl + b2s[4 * j4 + 1];
        o.z = h.z * sl + b2s[4 * j4 + 2];
        o.w = h.w * sl + b2s[4 * j4 + 3];
        *(float4*)&out[ob + 4 * j4] = o;
    }
}

// ------- layer 2 edge aggregation: 10 threads/edge -------------------------
__global__ __launch_bounds__(320) void k_agg2(float* __restrict__ out) {
    int idx = blockIdx.x * blockDim.x + threadIdx.x;    // E * 10 items
    int e = idx / 10;
    if (e >= N_EDGES) return;
    int c = (idx - e * 10) * 4;                         // float offset, 16B aligned
    int2 em = g_em[e];                                  // one broadcast LDG.64
    float nrm = g_dinv[em.x] * g_dinv[em.y];            // L2-hot broadcast loads
    float4 v = *(const float4*)&g_h2[(size_t)em.x * OUT_DIM + c];
    float* p = &out[(size_t)em.y * OUT_DIM + c];
    redg_v4(p, v.x * nrm, v.y * nrm, v.z * nrm, v.w * nrm);
}

// ---------------- launcher -------------------------------------------------
extern "C" void kernel_launch(void* const* d_in, const int* in_sizes, int n_in,
                              void* d_out, int out_size) {
    const float*    x  = (const float*)d_in[0];
    const unsigned* ei = (const unsigned*)d_in[1];   // int32 OR int64 words
    const float*    W1 = (const float*)d_in[2];
    const float*    b1 = (const float*)d_in[3];
    const float*    W2 = (const float*)d_in[4];
    const float*    b2 = (const float*)d_in[5];
    float* out = (float*)d_out;

    const int T = 256;
    k_detect <<<1, 32>>>(ei);
    k_extract<<<(N_EDGES + T - 1) / T, T>>>(ei);
    k_rsqrt  <<<(N_NODES + T - 1) / T, T>>>();
    k_gemm1  <<<(N_NODES + T - 1) / T, T>>>(x, W1);
    k_agg1   <<<(N_EDGES * 16 + T - 1) / T, T>>>();
    k_gemm2  <<<(N_NODES + T - 1) / T, T>>>(W2, b1, b2, out);
    k_agg2   <<<(N_EDGES * 10 + 319) / 320, 320>>>(out);
}

// round 15
// speedup vs baseline: 1.7068x; 1.0784x over previous
#include <cuda_runtime.h>
#include <cuda_bf16.h>

#define N_NODES 100000
#define N_EDGES 1600000
#define IN_DIM  128
#define HID_DIM 64
#define OUT_DIM 40

typedef unsigned long long ull;

// ---------------- packed f32x2 helpers (Blackwell FFMA2) -------------------
__device__ __forceinline__ ull pk2(float v) {              // {v, v}
    ull r; asm("mov.b64 %0, {%1, %1};" : "=l"(r) : "f"(v)); return r;
}
__device__ __forceinline__ ull pk2p(float lo, float hi) {  // {lo, hi}
    ull r; asm("mov.b64 %0, {%1, %2};" : "=l"(r) : "f"(lo), "f"(hi)); return r;
}
__device__ __forceinline__ void fma2(ull& d, ull a, ull b) {
    asm("fma.rn.f32x2 %0, %1, %2, %3;" : "=l"(d) : "l"(a), "l"(b), "l"(d));
}
__device__ __forceinline__ float2 up2(ull v) {
    float2 f; asm("mov.b64 {%0, %1}, %2;" : "=f"(f.x), "=f"(f.y) : "l"(v)); return f;
}

// ---------------- scratch (static device globals; no runtime alloc) --------
__device__              int    g_is64;
__device__              int    g_cd  [N_NODES];      // dst histogram; zero-init, reset each call
__device__ __align__(16) float g_dinv[N_NODES];
__device__ __align__(8)  int2  g_em  [N_EDGES];      // {src, dst}
__device__ __align__(16) float g_h1  [(size_t)N_NODES * HID_DIM];   // x@W1
__device__ __align__(16) float g_agg1[(size_t)N_NODES * HID_DIM];   // layer1 agg
__device__ __align__(16) float g_h2  [(size_t)N_NODES * OUT_DIM];   // relu(agg1+b1)@W2

__device__ __forceinline__ void redg_v4(float* p, float a, float b, float c, float d) {
    asm volatile("red.global.add.v4.f32 [%0], {%1, %2, %3, %4};"
                 :: "l"(p), "f"(a), "f"(b), "f"(c), "f"(d) : "memory");
}

// ---------------- dtype detection: int32 vs int64 edge_index ---------------
__global__ void k_detect(const unsigned* __restrict__ w) {
    if (threadIdx.x == 0 && blockIdx.x == 0) {
        int all0 = 1;
        for (int i = 0; i < 64; i++)
            if (w[2 * i + 1] != 0u) { all0 = 0; break; }
        g_is64 = all0;
    }
}

// extract {src,dst} as int2 (either stored width) + dst histogram
__global__ void k_extract(const unsigned* __restrict__ w) {
    int e = blockIdx.x * blockDim.x + threadIdx.x;
    if (e >= N_EDGES) return;
    int s, d;
    if (g_is64) {
        s = (int)w[2 * e];                           // low word of int64
        d = (int)w[2 * (N_EDGES + e)];
    } else {
        s = (int)w[e];
        d = (int)w[N_EDGES + e];
    }
    g_em[e] = make_int2(s, d);
    atomicAdd(&g_cd[d], 1);                          // int REDG
}

// dinv from in-degree; resets g_cd so the next call starts clean
__global__ void k_rsqrt() {
    int i = blockIdx.x * blockDim.x + threadIdx.x;
    if (i < N_NODES) {
        g_dinv[i] = rsqrtf((float)g_cd[i] + 1.0f);   // + self loop
        g_cd[i] = 0;
    }
}

// ------- layer 1 GEMM: 4 nodes x 16 cols per thread, f32x2 FMA -------------
__global__ __launch_bounds__(256) void k_gemm1(const float* __restrict__ x,
                                               const float* __restrict__ W1) {
    __shared__ float Ws[IN_DIM * HID_DIM];          // 32 KB
    {
        float4* dsh = (float4*)Ws;
        const float4* ssh = (const float4*)W1;
        for (int i = threadIdx.x; i < IN_DIM * HID_DIM / 4; i += blockDim.x)
            dsh[i] = ssh[i];
    }
    __syncthreads();

    int gid = blockIdx.x * blockDim.x + threadIdx.x;
    int quad = gid >> 2;
    if (quad >= N_NODES / 4) return;
    int cg = gid & 3;                               // 16-col group
    int n0 = quad * 4;
    const float* xb = x + (size_t)n0 * IN_DIM;

    ull acc[4][8];
#pragma unroll
    for (int ni = 0; ni < 4; ++ni)
#pragma unroll
        for (int j = 0; j < 8; ++j) acc[ni][j] = 0ull;

#pragma unroll 2
    for (int kk = 0; kk < IN_DIM / 4; ++kk) {
        float xv[4][4];
#pragma unroll
        for (int ni = 0; ni < 4; ++ni)
            *(float4*)xv[ni] = *(const float4*)(xb + ni * IN_DIM + kk * 4);
#pragma unroll
        for (int q = 0; q < 4; ++q) {
            const float4* wr = (const float4*)&Ws[(kk * 4 + q) * HID_DIM + cg * 16];
            ull wp[8];
#pragma unroll
            for (int j = 0; j < 4; ++j) {
                float4 w = wr[j];                   // LDS.128, conflict-free
                wp[2 * j]     = pk2p(w.x, w.y);
                wp[2 * j + 1] = pk2p(w.z, w.w);
            }
#pragma unroll
            for (int ni = 0; ni < 4; ++ni) {
                ull xp = pk2(xv[ni][q]);
#pragma unroll
                for (int j = 0; j < 8; ++j) fma2(acc[ni][j], wp[j], xp);
            }
        }
    }

#pragma unroll
    for (int ni = 0; ni < 4; ++ni) {
        int node = n0 + ni;
        float di = g_dinv[node];
        float sl = di * di;                         // self-loop coefficient
        size_t base = (size_t)node * HID_DIM + cg * 16;
#pragma unroll
        for (int j = 0; j < 4; ++j) {
            float2 a = up2(acc[ni][2 * j]);
            float2 b = up2(acc[ni][2 * j + 1]);
            float4 h; h.x = a.x; h.y = a.y; h.z = b.x; h.w = b.y;
            *(float4*)&g_h1[base + 4 * j] = h;
            float4 g; g.x = h.x * sl; g.y = h.y * sl; g.z = h.z * sl; g.w = h.w * sl;
            *(float4*)&g_agg1[base + 4 * j] = g;
        }
    }
}

// ------- layer 1 edge aggregation: 16 threads/edge, vector REDG.128 --------
__global__ __launch_bounds__(256) void k_agg1() {
    int idx = blockIdx.x * blockDim.x + threadIdx.x;    // E * 16 items
    if (idx >= N_EDGES * 16) return;
    int e = idx >> 4;
    int c = (idx & 15) << 2;                            // float offset, 16B aligned
    int2 em = g_em[e];                                  // one broadcast LDG.64
    float nrm = g_dinv[em.x] * g_dinv[em.y];            // L2-hot broadcast loads
    float4 v = *(const float4*)&g_h1[(size_t)em.x * HID_DIM + c];
    float* p = &g_agg1[(size_t)em.y * HID_DIM + c];
    redg_v4(p, v.x * nrm, v.y * nrm, v.z * nrm, v.w * nrm);
}

// ------- layer 2 GEMM: 2 nodes x 20 cols per thread, f32x2 FMA -------------
__global__ __launch_bounds__(256) void k_gemm2(const float* __restrict__ W2,
                                               const float* __restrict__ b1,
                                               const float* __restrict__ b2,
                                               float* __restrict__ out) {
    __shared__ float Ws[HID_DIM * OUT_DIM];         // 10 KB
    __shared__ float b1s[HID_DIM];
    __shared__ float b2s[OUT_DIM];
    for (int i = threadIdx.x; i < HID_DIM * OUT_DIM; i += blockDim.x) Ws[i] = W2[i];
    for (int i = threadIdx.x; i < HID_DIM; i += blockDim.x) b1s[i] = b1[i];
    for (int i = threadIdx.x; i < OUT_DIM; i += blockDim.x) b2s[i] = b2[i];
    __syncthreads();

    int gid = blockIdx.x * blockDim.x + threadIdx.x;
    int pair = gid >> 1;
    if (pair >= N_NODES / 2) return;
    int cg = gid & 1;                               // 20-col group
    int n0 = pair * 2;

    ull acc[2][10];
#pragma unroll
    for (int ni = 0; ni < 2; ++ni)
#pragma unroll
        for (int j = 0; j < 10; ++j) acc[ni][j] = 0ull;

#pragma unroll 2
    for (int kk = 0; kk < HID_DIM / 4; ++kk) {
        float vin[2][4];
#pragma unroll
        for (int ni = 0; ni < 2; ++ni) {
            float4 a = *(const float4*)&g_agg1[(size_t)(n0 + ni) * HID_DIM + kk * 4];
            vin[ni][0] = fmaxf(a.x + b1s[kk * 4 + 0], 0.0f);
            vin[ni][1] = fmaxf(a.y + b1s[kk * 4 + 1], 0.0f);
            vin[ni][2] = fmaxf(a.z + b1s[kk * 4 + 2], 0.0f);
            vin[ni][3] = fmaxf(a.w + b1s[kk * 4 + 3], 0.0f);
        }
#pragma unroll
        for (int q = 0; q < 4; ++q) {
            const float4* wr = (const float4*)&Ws[(kk * 4 + q) * OUT_DIM + cg * 20];
            ull wp[10];
#pragma unroll
            for (int j = 0; j < 5; ++j) {
                float4 w = wr[j];                   // LDS.128, conflict-free
                wp[2 * j]     = pk2p(w.x, w.y);
                wp[2 * j + 1] = pk2p(w.z, w.w);
            }
#pragma unroll
            for (int ni = 0; ni < 2; ++ni) {
                ull xp = pk2(vin[ni][q]);
#pragma unroll
                for (int j = 0; j < 10; ++j) fma2(acc[ni][j], wp[j], xp);
            }
        }
    }

#pragma unroll
    for (int ni = 0; ni < 2; ++ni) {
        int node = n0 + ni;
        float di = g_dinv[node];
        float sl = di * di;
        size_t base = (size_t)node * OUT_DIM + cg * 20;
#pragma unroll
        for (int j = 0; j < 5; ++j) {
            float2 a = up2(acc[ni][2 * j]);
            float2 b = up2(acc[ni][2 * j + 1]);
            float4 h; h.x = a.x; h.y = a.y; h.z = b.x; h.w = b.y;
            *(float4*)&g_h2[base + 4 * j] = h;
            float4 o;
            o.x = h.x * sl + b2s[cg * 20 + 4 * j + 0];
            o.y = h.y * sl + b2s[cg * 20 + 4 * j + 1];
            o.z = h.z * sl + b2s[cg * 20 + 4 * j + 2];
            o.w = h.w * sl + b2s[cg * 20 + 4 * j + 3];
            *(float4*)&out[base + 4 * j] = o;
        }
    }
}

// ------- layer 2 edge aggregation: 10 threads/edge -------------------------
__global__ __launch_bounds__(320) void k_agg2(float* __restrict__ out) {
    int idx = blockIdx.x * blockDim.x + threadIdx.x;    // E * 10 items
    int e = idx / 10;
    if (e >= N_EDGES) return;
    int c = (idx - e * 10) * 4;                         // float offset, 16B aligned
    int2 em = g_em[e];                                  // one broadcast LDG.64
    float nrm = g_dinv[em.x] * g_dinv[em.y];            // L2-hot broadcast loads
    float4 v = *(const float4*)&g_h2[(size_t)em.x * OUT_DIM + c];
    float* p = &out[(size_t)em.y * OUT_DIM + c];
    redg_v4(p, v.x * nrm, v.y * nrm, v.z * nrm, v.w * nrm);
}

// ---------------- launcher -------------------------------------------------
extern "C" void kernel_launch(void* const* d_in, const int* in_sizes, int n_in,
                              void* d_out, int out_size) {
    const float*    x  = (const float*)d_in[0];
    const unsigned* ei = (const unsigned*)d_in[1];   // int32 OR int64 words
    const float*    W1 = (const float*)d_in[2];
    const float*    b1 = (const float*)d_in[3];
    const float*    W2 = (const float*)d_in[4];
    const float*    b2 = (const float*)d_in[5];
    float* out = (float*)d_out;

    const int T = 256;
    k_detect <<<1, 32>>>(ei);
    k_extract<<<(N_EDGES + T - 1) / T, T>>>(ei);
    k_rsqrt  <<<(N_NODES + T - 1) / T, T>>>();
    k_gemm1  <<<(N_NODES + T - 1) / T, T>>>(x, W1);   // 100000 threads (25000 quads * 4)
    k_agg1   <<<(N_EDGES * 16 + T - 1) / T, T>>>();
    k_gemm2  <<<(N_NODES + T - 1) / T, T>>>(W2, b1, b2, out);  // 50000 pairs * 2
    k_agg2   <<<(N_EDGES * 10 + 319) / 320, 320>>>(out);
}